// round 8
// baseline (speedup 1.0000x reference)
#include <cuda_runtime.h>

#define MAX_SEG    4096
#define C_PER_SEG  4096          // per-segment index capacity (mean load ~49)
#define CHUNK      512
#define NBLK       1184          // 148 SMs x 8 blocks — guaranteed co-resident
#define NTHR       128

// Monotonic counters: never reset; each launch consumes an exact, fixed number
// of tickets, so epoch arithmetic is deterministic across graph replays.
__device__ unsigned int g_bar;          // barrier tickets: NBLK per launch
__device__ unsigned int g_work;         // work tickets: (n_seg + NBLK) per launch
__device__ int g_cursor[MAX_SEG];       // zeroed by phase 2 of the same launch
__device__ int g_nidx[MAX_SEG * C_PER_SEG];   // 64 MB strided CSR

__global__ void __launch_bounds__(NTHR, 8)
k_fused(const float* __restrict__ x, const void* __restrict__ labels,
        float* __restrict__ out, int dim, int n, int n_seg) {
    int tid = threadIdx.x;
    int dim4 = dim >> 2;               // 120 for dim=480

    __shared__ int sh[CHUNK];
    __shared__ int sh_seg;
    __shared__ unsigned int sh_epoch;

    // ---- dtype detect (block-local, branch-uniform) -----------------------
    // View labels as int32 words. int64 labels (< n_seg) have all odd words
    // zero; int32 labels have label values in odd words (nonzero among 128
    // samples w.p. 1-(1/4096)^128). Words [0, n) are in-bounds either way.
    const int* w32 = (const int*)labels;
    const long long* w64 = (const long long*)labels;
    int probe = 2 * tid + 1;
    int my = (probe < n) ? (w32[probe] != 0) : 0;
    int det = __syncthreads_or(my);    // 1 => labels are int32

    // ---- phase 1: scatter node indices into strided CSR -------------------
    for (int i = blockIdx.x * NTHR + tid; i < n; i += NBLK * NTHR) {
        int s = det ? w32[i] : (int)w64[i];
        int p = atomicAdd(&g_cursor[s], 1);
        if (p < C_PER_SEG) g_nidx[s * C_PER_SEG + p] = i;
    }

    // ---- grid barrier (ticket-epoch, monotonic, no reset) ------------------
    if (tid == 0) {
        __threadfence();                              // publish scatter writes
        unsigned int t = atomicAdd(&g_bar, 1u);
        unsigned int epoch = t / NBLK;                // same for all blocks this launch
        unsigned int target = (epoch + 1u) * NBLK;
        while (*(volatile unsigned int*)&g_bar < target)
            __nanosleep(64);
        __threadfence();                              // acquire
        sh_epoch = epoch;
    }
    __syncthreads();
    unsigned int work_base = sh_epoch * (unsigned int)(n_seg + NBLK);

    // ---- phase 2: per-segment gather + mean (dynamic scheduling) ----------
    // Each launch consumes exactly n_seg + NBLK work tickets: every success
    // ticket is drawn, and every block terminates on exactly one failing one.
    for (;;) {
        if (tid == 0)
            sh_seg = (int)(atomicAdd(&g_work, 1u) - work_base);
        __syncthreads();
        int seg = sh_seg;
        __syncthreads();
        if (seg >= n_seg) break;

        int cnt = g_cursor[seg];
        float4 acc = make_float4(0.f, 0.f, 0.f, 0.f);

        if (cnt <= C_PER_SEG) {
            const int* idx = g_nidx + seg * C_PER_SEG;
            for (int base = 0; base < cnt; base += CHUNK) {
                int m = min(CHUNK, cnt - base);
                __syncthreads();
                for (int i = tid; i < m; i += NTHR)
                    sh[i] = idx[base + i];
                __syncthreads();

                if (tid < dim4) {
                    int j = 0;
                    for (; j + 8 <= m; j += 8) {
                        float4 v0 = ((const float4*)(x + (size_t)sh[j + 0] * dim))[tid];
                        float4 v1 = ((const float4*)(x + (size_t)sh[j + 1] * dim))[tid];
                        float4 v2 = ((const float4*)(x + (size_t)sh[j + 2] * dim))[tid];
                        float4 v3 = ((const float4*)(x + (size_t)sh[j + 3] * dim))[tid];
                        float4 v4 = ((const float4*)(x + (size_t)sh[j + 4] * dim))[tid];
                        float4 v5 = ((const float4*)(x + (size_t)sh[j + 5] * dim))[tid];
                        float4 v6 = ((const float4*)(x + (size_t)sh[j + 6] * dim))[tid];
                        float4 v7 = ((const float4*)(x + (size_t)sh[j + 7] * dim))[tid];
                        acc.x += ((v0.x + v1.x) + (v2.x + v3.x)) + ((v4.x + v5.x) + (v6.x + v7.x));
                        acc.y += ((v0.y + v1.y) + (v2.y + v3.y)) + ((v4.y + v5.y) + (v6.y + v7.y));
                        acc.z += ((v0.z + v1.z) + (v2.z + v3.z)) + ((v4.z + v5.z) + (v6.z + v7.z));
                        acc.w += ((v0.w + v1.w) + (v2.w + v3.w)) + ((v4.w + v5.w) + (v6.w + v7.w));
                    }
                    for (; j < m; j++) {
                        float4 v = ((const float4*)(x + (size_t)sh[j] * dim))[tid];
                        acc.x += v.x; acc.y += v.y; acc.z += v.z; acc.w += v.w;
                    }
                }
            }
        } else {
            // overflow fallback (never for realistic inputs): scan labels
            for (int i = 0; i < n; i++) {
                int l = det ? w32[i] : (int)w64[i];
                if (l == seg && tid < dim4) {
                    float4 v = ((const float4*)(x + (size_t)i * dim))[tid];
                    acc.x += v.x; acc.y += v.y; acc.z += v.z; acc.w += v.w;
                }
            }
        }

        if (tid < dim4) {
            float inv = 1.0f / (float)max(cnt, 1);
            float4 o;
            o.x = acc.x * inv;
            o.y = acc.y * inv;
            o.z = acc.z * inv;
            o.w = acc.w * inv;
            ((float4*)(out + (size_t)seg * dim))[tid] = o;
        }

        // self-clean this segment's cursor for the next launch (safe: every
        // segment is processed by exactly one block, after the barrier)
        if (tid == NTHR - 1) g_cursor[seg] = 0;
    }
}

// ---------------------------------------------------------------- launch
extern "C" void kernel_launch(void* const* d_in, const int* in_sizes, int n_in,
                              void* d_out, int out_size) {
    const float* x      = (const float*)d_in[0];
    const void*  labels = d_in[1];
    float*       out    = (float*)d_out;

    int n_nodes = in_sizes[1];
    int dim     = in_sizes[0] / n_nodes;      // 480
    int n_seg   = out_size / dim;             // 4096

    k_fused<<<NBLK, NTHR>>>(x, labels, out, dim, n_nodes, n_seg);
}